// round 13
// baseline (speedup 1.0000x reference)
#include <cuda_runtime.h>
#include <cuda_fp16.h>
#include <math.h>
#include <cstdint>

// ---------------------------------------------------------------------------
// Problem constants
// ---------------------------------------------------------------------------
#define B  4
#define S  4096
#define H  1024
#define NH 16
#define D  64
#define SCALE 0.125f

#define GM (B*S)   // 16384
#define GN H       // 1024
#define GK H       // 1024

#define CTX_ELEMS ((size_t)B * S * H)

// ---------------------------------------------------------------------------
// Device scratch (allocation-free)
// ---------------------------------------------------------------------------
__device__ __half g_q[B * S * H];
__device__ __half g_k[B * S * H];
__device__ __half g_v[B * S * H];

__device__ __half g_ah[(size_t)GM * GK];
__device__ __half g_wh[3][(size_t)GN * GK];

#define GCH 16
__device__ float g_pmax[B * NH][GCH];
__device__ float g_psum[B * NH][GCH];
__device__ float g_pvac[B * NH][GCH][D];
__device__ int   g_ticket[B * NH];          // zero-init; self-cleaning

// ---------------------------------------------------------------------------
// Helpers
// ---------------------------------------------------------------------------
__device__ __forceinline__ uint32_t smem_u32(const void* p) {
    uint32_t a;
    asm("{ .reg .u64 t; cvta.to.shared.u64 t, %1; cvt.u32.u64 %0, t; }"
        : "=r"(a) : "l"(p));
    return a;
}

__device__ __forceinline__ void cp16(uint32_t dst, const void* src) {
    asm volatile("cp.async.cg.shared.global [%0], [%1], 16;"
                 :: "r"(dst), "l"(src));
}
#define CP_COMMIT() asm volatile("cp.async.commit_group;" ::: "memory")
#define CP_WAIT0()  asm volatile("cp.async.wait_group 0;" ::: "memory")

__device__ __forceinline__ void ldsm4(uint32_t* r, uint32_t addr) {
    asm volatile("ldmatrix.sync.aligned.m8n8.x4.shared.b16 {%0,%1,%2,%3}, [%4];"
                 : "=r"(r[0]), "=r"(r[1]), "=r"(r[2]), "=r"(r[3]) : "r"(addr));
}

__device__ __forceinline__ void mma16816h(float* c, const uint32_t* a,
                                          uint32_t b0, uint32_t b1) {
    asm volatile(
        "mma.sync.aligned.m16n8k16.row.col.f32.f16.f16.f32 "
        "{%0,%1,%2,%3}, {%4,%5,%6,%7}, {%8,%9}, {%0,%1,%2,%3};"
        : "+f"(c[0]), "+f"(c[1]), "+f"(c[2]), "+f"(c[3])
        : "r"(a[0]), "r"(a[1]), "r"(a[2]), "r"(a[3]), "r"(b0), "r"(b1));
}

// ---------------------------------------------------------------------------
// Unified convert: hidden + Wq/Wk/Wv -> fp16.
// ---------------------------------------------------------------------------
#define HN8 ((GM * GK) / 8)
#define WN8 ((GN * GK) / 8)
#define TOTN8 (HN8 + 3 * WN8)

__global__ __launch_bounds__(256) void split_all(
    const float* __restrict__ hidden,
    const float* __restrict__ Wq,
    const float* __restrict__ Wk,
    const float* __restrict__ Wv)
{
    int i = blockIdx.x * blockDim.x + threadIdx.x;
    if (i >= TOTN8) return;

    const float* src;
    __half* dst;
    size_t off;
    if (i < HN8) {
        src = hidden; dst = g_ah; off = (size_t)i * 8;
    } else {
        int j0 = i - HN8;
        int w = j0 / WN8;
        off = (size_t)(j0 - w * WN8) * 8;
        src = (w == 0) ? Wq : (w == 1) ? Wk : Wv;
        dst = g_wh[w];
    }

    const float4* xp = (const float4*)(src + off);
    float4 a = xp[0], b = xp[1];
    float f[8] = {a.x, a.y, a.z, a.w, b.x, b.y, b.z, b.w};
    __align__(16) __half h[8];
    #pragma unroll
    for (int j = 0; j < 8; j++) h[j] = __float2half_rn(f[j]);
    *(uint4*)(dst + off) = *(uint4*)h;
}

// ---------------------------------------------------------------------------
// QKV GEMM via mma.sync fp16, fp32 accum, fp16 output.  (R10 shape — proven)
// ---------------------------------------------------------------------------
#define TM 256
#define TN 128
#define TKC 128
#define NCHUNK (GK / TKC)                  // 8
#define AT_B  (TM * 64 * 2)
#define BT_B  (TN * 64 * 2)
#define OFF_A0 0
#define OFF_A1 AT_B
#define OFF_B0 (2 * AT_B)
#define OFF_B1 (2 * AT_B + BT_B)
#define STAGE_B (2 * AT_B + 2 * BT_B)      // 98304
#define GSMEM  (2 * STAGE_B)               // 196608

__global__ __launch_bounds__(256, 1) void qkv_gemm_mma(
    const float* __restrict__ bias_q,
    const float* __restrict__ bias_k,
    const float* __restrict__ bias_v)
{
    extern __shared__ __align__(1024) char sb[];

    const int z  = blockIdx.z;
    const int bm = blockIdx.y * TM;
    const int bn = blockIdx.x * TN;

    const __half* Ah = g_ah;
    const __half* Bh = g_wh[z];
    const float* bias = (z == 0) ? bias_q : (z == 1) ? bias_k : bias_v;
    __half* Cout = (z == 0) ? g_q : (z == 1) ? g_k : g_v;

    const int tid  = threadIdx.x;
    const int wid  = tid >> 5;
    const int lane = tid & 31;
    const int wm   = (wid >> 1) * 64;
    const int wn   = (wid & 1) * 64;

    const uint32_t sbase = smem_u32(sb);

    auto load_chunk = [&](int c, int buf) {
        const int kc = c * TKC;
        const uint32_t stage = sbase + buf * STAGE_B;
        #pragma unroll
        for (int sub = 0; sub < 2; sub++) {
            uint32_t dtile = stage + (sub ? OFF_A1 : OFF_A0);
            const int kb = kc + sub * 64;
            #pragma unroll
            for (int i = 0; i < 8; i++) {
                int idx = tid + i * 256;
                int row = idx >> 3;
                int v   = idx & 7;
                uint32_t off = (uint32_t)(row << 7) + (uint32_t)(v << 4);
                off ^= ((uint32_t)(row & 7) << 4);
                cp16(dtile + off, Ah + (size_t)(bm + row) * GK + kb + v * 8);
            }
        }
        #pragma unroll
        for (int sub = 0; sub < 2; sub++) {
            uint32_t dtile = stage + (sub ? OFF_B1 : OFF_B0);
            const int kb = kc + sub * 64;
            #pragma unroll
            for (int i = 0; i < 4; i++) {
                int idx = tid + i * 256;
                int row = idx >> 3;
                int v   = idx & 7;
                uint32_t off = (uint32_t)(row << 7) + (uint32_t)(v << 4);
                off ^= ((uint32_t)(row & 7) << 4);
                cp16(dtile + off, Bh + (size_t)(bn + row) * GK + kb + v * 8);
            }
        }
    };

    float acc[4][8][4];
    #pragma unroll
    for (int f = 0; f < 4; f++)
        #pragma unroll
        for (int g = 0; g < 8; g++)
            #pragma unroll
            for (int j = 0; j < 4; j++) acc[f][g][j] = 0.f;

    const int a_row_l = lane & 15;
    const int a_kb_l  = (lane >> 4) << 4;
    const int b_row_l = (lane & 7) + ((lane >> 4) << 3);
    const int b_kb_l  = ((lane >> 3) & 1) << 4;

    load_chunk(0, 0);
    CP_COMMIT();

    for (int c = 0; c < NCHUNK; c++) {
        const int buf = c & 1;
        CP_WAIT0();
        __syncthreads();
        if (c + 1 < NCHUNK) {
            load_chunk(c + 1, buf ^ 1);
            CP_COMMIT();
        }

        const uint32_t stage = sbase + buf * STAGE_B;

        #pragma unroll
        for (int sub = 0; sub < 2; sub++) {
            const uint32_t baseA = stage + (sub ? OFF_A1 : OFF_A0);
            const uint32_t baseB = stage + (sub ? OFF_B1 : OFF_B0);
            #pragma unroll
            for (int s = 0; s < 4; s++) {
                uint32_t aF[4][4], bH[4][4];
                const uint32_t cbA = (uint32_t)(s * 32 + a_kb_l);
                const uint32_t cbB = (uint32_t)(s * 32 + b_kb_l);
                #pragma unroll
                for (int f = 0; f < 4; f++) {
                    int row = wm + f * 16 + a_row_l;
                    uint32_t off = (uint32_t)(row << 7) + (cbA ^ ((uint32_t)(row & 7) << 4));
                    ldsm4(aF[f], baseA + off);
                }
                #pragma unroll
                for (int g16 = 0; g16 < 4; g16++) {
                    int row = wn + g16 * 16 + b_row_l;
                    uint32_t off = (uint32_t)(row << 7) + (cbB ^ ((uint32_t)(row & 7) << 4));
                    ldsm4(bH[g16], baseB + off);
                }
                #pragma unroll
                for (int f = 0; f < 4; f++) {
                    #pragma unroll
                    for (int g16 = 0; g16 < 4; g16++) {
                        #pragma unroll
                        for (int p = 0; p < 2; p++) {
                            float* cc = acc[f][g16 * 2 + p];
                            mma16816h(cc, aF[f], bH[g16][2*p], bH[g16][2*p+1]);
                        }
                    }
                }
            }
        }
    }

    #pragma unroll
    for (int f = 0; f < 4; f++) {
        #pragma unroll
        for (int g = 0; g < 8; g++) {
            int row = bm + wm + f * 16 + (lane >> 2);
            int col = bn + wn + g * 8 + (lane & 3) * 2;
            float b0 = bias[col], b1 = bias[col + 1];
            __half2 h0 = __floats2half2_rn(acc[f][g][0] + b0, acc[f][g][1] + b1);
            __half2 h1 = __floats2half2_rn(acc[f][g][2] + b0, acc[f][g][3] + b1);
            *(__half2*)(Cout + (size_t)row * GN + col)       = h0;
            *(__half2*)(Cout + (size_t)(row + 8) * GN + col) = h1;
        }
    }
}

// ---------------------------------------------------------------------------
// Single-pass fused attention (online softmax) + inline combine.
// grid (GCH, B*NH), block 256 (8 warps x 32 rows).
// ---------------------------------------------------------------------------
#define SCHUNK (S / GCH)   // 256
#define RPW (SCHUNK / 8)   // 32 rows per warp

__global__ __launch_bounds__(256) void gl_attn(
    const float* __restrict__ mask, float* __restrict__ out)
{
    const int ch = blockIdx.x;
    const int bh = blockIdx.y;
    const int b  = bh / NH;
    const int h  = bh % NH;

    __shared__ float sq0[D], sk0[D], sv0[D];
    __shared__ float rmax[8], rsum[8];
    __shared__ float vwarp[8][D];
    __shared__ bool  is_last;

    const int tid  = threadIdx.x;
    const int lane = tid & 31;
    const int w    = tid >> 5;

    const size_t base0 = ((size_t)b * S) * H + (size_t)h * D;
    if (tid < D) {
        sq0[tid] = __half2float(g_q[base0 + tid]);
        sk0[tid] = __half2float(g_k[base0 + tid]);
        sv0[tid] = __half2float(g_v[base0 + tid]);
    }
    __syncthreads();

    const float q00 = sq0[2 * lane], q01 = sq0[2 * lane + 1];
    const float k00 = sk0[2 * lane], k01 = sk0[2 * lane + 1];
    const float v00 = sv0[2 * lane], v01 = sv0[2 * lane + 1];

    const int s0 = ch * SCHUNK + w * RPW;

    // single pass: local attention output + online-softmax global accumulation
    float lm = -INFINITY;   // running max (same on all lanes)
    float lsum = 0.f;       // running sum (same on all lanes; lane0 authoritative)
    float a0 = 0.f, a1 = 0.f;

    #pragma unroll 2
    for (int i = 0; i < RPW; i++) {
        const int s = s0 + i;
        const size_t bs = ((size_t)b * S + s) * H + (size_t)h * D;
        float2 q2 = __half22float2(((const __half2*)(g_q + bs))[lane]);
        float2 k2 = __half22float2(((const __half2*)(g_k + bs))[lane]);
        float2 v2 = __half22float2(((const __half2*)(g_v + bs))[lane]);

        float dg = q00 * k2.x + q01 * k2.y;   // gq . k_s
        float ds = q2.x * k2.x + q2.y * k2.y; // q_s . k_s
        float dl = q2.x * k00 + q2.y * k01;   // q_s . k_0
        #pragma unroll
        for (int o = 16; o; o >>= 1) {
            dg += __shfl_xor_sync(~0u, dg, o);
            ds += __shfl_xor_sync(~0u, ds, o);
            dl += __shfl_xor_sync(~0u, dl, o);
        }

        // local 2-way softmax + output (all lanes redundantly compute probs)
        if (s != 0) {
            float ps = ds * SCALE, pg = dl * SCALE;
            float m  = fmaxf(ps, pg);
            float e0 = expf(ps - m), e1 = expf(pg - m);
            float inv = 1.f / (e0 + e1);
            float p0 = e0 * inv, p1 = e1 * inv;
            float2 o2 = make_float2(p0 * v2.x + p1 * v00,
                                    p0 * v2.y + p1 * v01);
            ((float2*)(out + bs))[lane] = o2;
            if (lane == 0) {
                size_t li = CTX_ELEMS + ((size_t)bh * (S - 1) + (s - 1)) * 2;
                out[li]     = p0;
                out[li + 1] = p1;
            }
        }

        // global: online softmax accumulate
        float g = dg * SCALE + mask[(size_t)b * S + s];
        float nm = fmaxf(lm, g);
        float sc = expf(lm - nm);      // lm=-inf first iter -> 0
        float pe = expf(g - nm);
        a0 = a0 * sc + pe * v2.x;
        a1 = a1 * sc + pe * v2.y;
        lsum = lsum * sc + pe;
        lm = nm;
    }

    vwarp[w][2 * lane]     = a0;
    vwarp[w][2 * lane + 1] = a1;
    if (lane == 0) { rmax[w] = lm; rsum[w] = lsum; }
    __syncthreads();

    // combine 8 warps -> chunk partial
    if (tid < D) {
        float bmax = rmax[0];
        #pragma unroll
        for (int ww = 1; ww < 8; ww++) bmax = fmaxf(bmax, rmax[ww]);
        float vs = 0.f, bsum = 0.f;
        #pragma unroll
        for (int ww = 0; ww < 8; ww++) {
            float sc = expf(rmax[ww] - bmax);
            vs   += vwarp[ww][tid] * sc;
            bsum += rsum[ww] * sc;
        }
        g_pvac[bh][ch][tid] = vs;
        if (tid == 0) {
            g_pmax[bh][ch] = bmax;
            g_psum[bh][ch] = bsum;
        }
    }
    __syncthreads();

    // ticket: last block of this bh combines across chunks
    if (tid == 0) {
        __threadfence();
        int cnt = atomicAdd(&g_ticket[bh], 1);
        is_last = (cnt == GCH - 1);
    }
    __syncthreads();

    if (is_last) {
        if (tid == 0) {
            g_ticket[bh] = 0;              // self-clean for graph replay
            __threadfence();
        }
        if (tid < D) {
            float M = -INFINITY;
            #pragma unroll
            for (int c = 0; c < GCH; c++) M = fmaxf(M, g_pmax[bh][c]);
            float denom = 0.f, vs = 0.f;
            #pragma unroll
            for (int c = 0; c < GCH; c++) {
                float sc = expf(g_pmax[bh][c] - M);
                denom += g_psum[bh][c] * sc;
                vs    += g_pvac[bh][c][tid] * sc;
            }
            out[base0 + tid] = vs / denom;
        }
    }
}

// ---------------------------------------------------------------------------
extern "C" void kernel_launch(void* const* d_in, const int* in_sizes, int n_in,
                              void* d_out, int out_size)
{
    const float* hidden = (const float*)d_in[0];
    const float* mask   = (const float*)d_in[1];
    const float* Wq     = (const float*)d_in[2];
    const float* bq     = (const float*)d_in[3];
    const float* Wk     = (const float*)d_in[4];
    const float* bk     = (const float*)d_in[5];
    const float* Wv     = (const float*)d_in[6];
    const float* bv     = (const float*)d_in[7];
    float* out = (float*)d_out;

    split_all<<<(TOTN8 + 255) / 256, 256>>>(hidden, Wq, Wk, Wv);

    cudaFuncSetAttribute(qkv_gemm_mma, cudaFuncAttributeMaxDynamicSharedMemorySize, GSMEM);
    dim3 ggrid(GN / TN, GM / TM, 3);   // (8, 64, 3) = 1536 CTAs
    qkv_gemm_mma<<<ggrid, 256, GSMEM>>>(bq, bk, bv);

    dim3 agrid(GCH, B * NH);
    gl_attn<<<agrid, 256>>>(mask, out);
}

// round 14
// speedup vs baseline: 1.0182x; 1.0182x over previous
#include <cuda_runtime.h>
#include <cuda_fp16.h>
#include <math.h>
#include <cstdint>

// ---------------------------------------------------------------------------
// Problem constants
// ---------------------------------------------------------------------------
#define B  4
#define S  4096
#define H  1024
#define NH 16
#define D  64
#define SCALE 0.125f

#define GM (B*S)   // 16384
#define GN H       // 1024
#define GK H       // 1024

#define CTX_ELEMS ((size_t)B * S * H)

// ---------------------------------------------------------------------------
// Device scratch (allocation-free)
// ---------------------------------------------------------------------------
__device__ __half g_q[B * S * H];
__device__ __half g_k[B * S * H];
__device__ __half g_v[B * S * H];

__device__ __half g_ah[(size_t)GM * GK];
__device__ __half g_wh[3][(size_t)GN * GK];

#define GCH 16
__device__ float g_pmax[B * NH][GCH];
__device__ float g_psum[B * NH][GCH];
__device__ float g_pvac[B * NH][GCH][D];

// ---------------------------------------------------------------------------
// Helpers
// ---------------------------------------------------------------------------
__device__ __forceinline__ uint32_t smem_u32(const void* p) {
    uint32_t a;
    asm("{ .reg .u64 t; cvta.to.shared.u64 t, %1; cvt.u32.u64 %0, t; }"
        : "=r"(a) : "l"(p));
    return a;
}

__device__ __forceinline__ void cp16(uint32_t dst, const void* src) {
    asm volatile("cp.async.cg.shared.global [%0], [%1], 16;"
                 :: "r"(dst), "l"(src));
}
#define CP_COMMIT() asm volatile("cp.async.commit_group;" ::: "memory")
#define CP_WAIT0()  asm volatile("cp.async.wait_group 0;" ::: "memory")

__device__ __forceinline__ void ldsm4(uint32_t* r, uint32_t addr) {
    asm volatile("ldmatrix.sync.aligned.m8n8.x4.shared.b16 {%0,%1,%2,%3}, [%4];"
                 : "=r"(r[0]), "=r"(r[1]), "=r"(r[2]), "=r"(r[3]) : "r"(addr));
}

__device__ __forceinline__ void mma16816h(float* c, const uint32_t* a,
                                          uint32_t b0, uint32_t b1) {
    asm volatile(
        "mma.sync.aligned.m16n8k16.row.col.f32.f16.f16.f32 "
        "{%0,%1,%2,%3}, {%4,%5,%6,%7}, {%8,%9}, {%0,%1,%2,%3};"
        : "+f"(c[0]), "+f"(c[1]), "+f"(c[2]), "+f"(c[3])
        : "r"(a[0]), "r"(a[1]), "r"(a[2]), "r"(a[3]), "r"(b0), "r"(b1));
}

// ---------------------------------------------------------------------------
// Unified convert: hidden + Wq/Wk/Wv -> fp16. 16 floats per thread (MLP=2).
// ---------------------------------------------------------------------------
#define HN16 ((GM * GK) / 16)     // 1,048,576
#define WN16 ((GN * GK) / 16)     // 65,536
#define TOTN16 (HN16 + 3 * WN16)  // 1,245,184

__global__ __launch_bounds__(256) void split_all(
    const float* __restrict__ hidden,
    const float* __restrict__ Wq,
    const float* __restrict__ Wk,
    const float* __restrict__ Wv)
{
    int i = blockIdx.x * blockDim.x + threadIdx.x;
    if (i >= TOTN16) return;

    const float* src;
    __half* dst;
    size_t off;
    if (i < HN16) {
        src = hidden; dst = g_ah; off = (size_t)i * 16;
    } else {
        int j0 = i - HN16;
        int w = j0 / WN16;
        off = (size_t)(j0 - w * WN16) * 16;
        src = (w == 0) ? Wq : (w == 1) ? Wk : Wv;
        dst = g_wh[w];
    }

    const float4* xp = (const float4*)(src + off);
    float4 a = xp[0], b = xp[1], c = xp[2], d = xp[3];
    float f[16] = {a.x, a.y, a.z, a.w, b.x, b.y, b.z, b.w,
                   c.x, c.y, c.z, c.w, d.x, d.y, d.z, d.w};
    __align__(16) __half h[16];
    #pragma unroll
    for (int j = 0; j < 16; j++) h[j] = __float2half_rn(f[j]);
    ((uint4*)(dst + off))[0] = ((uint4*)h)[0];
    ((uint4*)(dst + off))[1] = ((uint4*)h)[1];
}

// ---------------------------------------------------------------------------
// QKV GEMM via mma.sync fp16, fp32 accum, fp16 output.  (R10 shape — proven)
// Block tile 256(M) x 128(N), K-chunk 128, 2-stage, ONE sync per chunk.
// ---------------------------------------------------------------------------
#define TM 256
#define TN 128
#define TKC 128
#define NCHUNK (GK / TKC)                  // 8
#define AT_B  (TM * 64 * 2)
#define BT_B  (TN * 64 * 2)
#define OFF_A0 0
#define OFF_A1 AT_B
#define OFF_B0 (2 * AT_B)
#define OFF_B1 (2 * AT_B + BT_B)
#define STAGE_B (2 * AT_B + 2 * BT_B)      // 98304
#define GSMEM  (2 * STAGE_B)               // 196608

__global__ __launch_bounds__(256, 1) void qkv_gemm_mma(
    const float* __restrict__ bias_q,
    const float* __restrict__ bias_k,
    const float* __restrict__ bias_v)
{
    extern __shared__ __align__(1024) char sb[];

    const int z  = blockIdx.z;
    const int bm = blockIdx.y * TM;
    const int bn = blockIdx.x * TN;

    const __half* Ah = g_ah;
    const __half* Bh = g_wh[z];
    const float* bias = (z == 0) ? bias_q : (z == 1) ? bias_k : bias_v;
    __half* Cout = (z == 0) ? g_q : (z == 1) ? g_k : g_v;

    const int tid  = threadIdx.x;
    const int wid  = tid >> 5;
    const int lane = tid & 31;
    const int wm   = (wid >> 1) * 64;
    const int wn   = (wid & 1) * 64;

    const uint32_t sbase = smem_u32(sb);

    auto load_chunk = [&](int c, int buf) {
        const int kc = c * TKC;
        const uint32_t stage = sbase + buf * STAGE_B;
        #pragma unroll
        for (int sub = 0; sub < 2; sub++) {
            uint32_t dtile = stage + (sub ? OFF_A1 : OFF_A0);
            const int kb = kc + sub * 64;
            #pragma unroll
            for (int i = 0; i < 8; i++) {
                int idx = tid + i * 256;
                int row = idx >> 3;
                int v   = idx & 7;
                uint32_t off = (uint32_t)(row << 7) + (uint32_t)(v << 4);
                off ^= ((uint32_t)(row & 7) << 4);
                cp16(dtile + off, Ah + (size_t)(bm + row) * GK + kb + v * 8);
            }
        }
        #pragma unroll
        for (int sub = 0; sub < 2; sub++) {
            uint32_t dtile = stage + (sub ? OFF_B1 : OFF_B0);
            const int kb = kc + sub * 64;
            #pragma unroll
            for (int i = 0; i < 4; i++) {
                int idx = tid + i * 256;
                int row = idx >> 3;
                int v   = idx & 7;
                uint32_t off = (uint32_t)(row << 7) + (uint32_t)(v << 4);
                off ^= ((uint32_t)(row & 7) << 4);
                cp16(dtile + off, Bh + (size_t)(bn + row) * GK + kb + v * 8);
            }
        }
    };

    float acc[4][8][4];
    #pragma unroll
    for (int f = 0; f < 4; f++)
        #pragma unroll
        for (int g = 0; g < 8; g++)
            #pragma unroll
            for (int j = 0; j < 4; j++) acc[f][g][j] = 0.f;

    const int a_row_l = lane & 15;
    const int a_kb_l  = (lane >> 4) << 4;
    const int b_row_l = (lane & 7) + ((lane >> 4) << 3);
    const int b_kb_l  = ((lane >> 3) & 1) << 4;

    load_chunk(0, 0);
    CP_COMMIT();

    for (int c = 0; c < NCHUNK; c++) {
        const int buf = c & 1;
        CP_WAIT0();
        __syncthreads();
        if (c + 1 < NCHUNK) {
            load_chunk(c + 1, buf ^ 1);
            CP_COMMIT();
        }

        const uint32_t stage = sbase + buf * STAGE_B;

        #pragma unroll
        for (int sub = 0; sub < 2; sub++) {
            const uint32_t baseA = stage + (sub ? OFF_A1 : OFF_A0);
            const uint32_t baseB = stage + (sub ? OFF_B1 : OFF_B0);
            #pragma unroll
            for (int s = 0; s < 4; s++) {
                uint32_t aF[4][4], bH[4][4];
                const uint32_t cbA = (uint32_t)(s * 32 + a_kb_l);
                const uint32_t cbB = (uint32_t)(s * 32 + b_kb_l);
                #pragma unroll
                for (int f = 0; f < 4; f++) {
                    int row = wm + f * 16 + a_row_l;
                    uint32_t off = (uint32_t)(row << 7) + (cbA ^ ((uint32_t)(row & 7) << 4));
                    ldsm4(aF[f], baseA + off);
                }
                #pragma unroll
                for (int g16 = 0; g16 < 4; g16++) {
                    int row = wn + g16 * 16 + b_row_l;
                    uint32_t off = (uint32_t)(row << 7) + (cbB ^ ((uint32_t)(row & 7) << 4));
                    ldsm4(bH[g16], baseB + off);
                }
                #pragma unroll
                for (int f = 0; f < 4; f++) {
                    #pragma unroll
                    for (int g16 = 0; g16 < 4; g16++) {
                        #pragma unroll
                        for (int p = 0; p < 2; p++) {
                            float* cc = acc[f][g16 * 2 + p];
                            mma16816h(cc, aF[f], bH[g16][2*p], bH[g16][2*p+1]);
                        }
                    }
                }
            }
        }
    }

    // ---- epilogue: bias + fp16 store ----
    #pragma unroll
    for (int f = 0; f < 4; f++) {
        #pragma unroll
        for (int g = 0; g < 8; g++) {
            int row = bm + wm + f * 16 + (lane >> 2);
            int col = bn + wn + g * 8 + (lane & 3) * 2;
            float b0 = bias[col], b1 = bias[col + 1];
            __half2 h0 = __floats2half2_rn(acc[f][g][0] + b0, acc[f][g][1] + b1);
            __half2 h1 = __floats2half2_rn(acc[f][g][2] + b0, acc[f][g][3] + b1);
            *(__half2*)(Cout + (size_t)row * GN + col)       = h0;
            *(__half2*)(Cout + (size_t)(row + 8) * GN + col) = h1;
        }
    }
}

// ---------------------------------------------------------------------------
// Fused attention (two-pass, R10 shape): grid (GCH, B*NH), block 256.
// ---------------------------------------------------------------------------
#define SCHUNK (S / GCH)   // 256
#define RPW (SCHUNK / 8)   // 32 rows per warp

__global__ __launch_bounds__(256) void gl_attn(
    const float* __restrict__ mask, float* __restrict__ out)
{
    const int ch = blockIdx.x;
    const int bh = blockIdx.y;
    const int b  = bh / NH;
    const int h  = bh % NH;

    __shared__ float sq0[D], sk0[D], sv0[D];
    __shared__ float gsc[SCHUNK];
    __shared__ float sp0[SCHUNK], sp1[SCHUNK];
    __shared__ float red[8];
    __shared__ float vwarp[8][D];

    const int tid  = threadIdx.x;
    const int lane = tid & 31;
    const int w    = tid >> 5;

    const size_t base0 = ((size_t)b * S) * H + (size_t)h * D;
    if (tid < D) {
        sq0[tid] = __half2float(g_q[base0 + tid]);
        sk0[tid] = __half2float(g_k[base0 + tid]);
        sv0[tid] = __half2float(g_v[base0 + tid]);
    }
    __syncthreads();

    const float q00 = sq0[2 * lane], q01 = sq0[2 * lane + 1];
    const float k00 = sk0[2 * lane], k01 = sk0[2 * lane + 1];
    const float v00 = sv0[2 * lane], v01 = sv0[2 * lane + 1];

    const int row0 = w * RPW;
    const int s0   = ch * SCHUNK + row0;

    // phase 1: scores (global + local 2-way softmax)
    #pragma unroll 2
    for (int i = 0; i < RPW; i++) {
        const int s = s0 + i;
        const size_t bs = ((size_t)b * S + s) * H + (size_t)h * D;
        float2 q2 = __half22float2(((const __half2*)(g_q + bs))[lane]);
        float2 k2 = __half22float2(((const __half2*)(g_k + bs))[lane]);

        float dg = q00 * k2.x + q01 * k2.y;
        float ds = q2.x * k2.x + q2.y * k2.y;
        float dl = q2.x * k00 + q2.y * k01;
        #pragma unroll
        for (int o = 16; o; o >>= 1) {
            dg += __shfl_xor_sync(~0u, dg, o);
            ds += __shfl_xor_sync(~0u, ds, o);
            dl += __shfl_xor_sync(~0u, dl, o);
        }
        if (lane == 0) {
            gsc[row0 + i] = dg * SCALE + mask[(size_t)b * S + s];
            float ps = ds * SCALE, pg = dl * SCALE;
            float m  = fmaxf(ps, pg);
            float e0 = expf(ps - m), e1 = expf(pg - m);
            float inv = 1.f / (e0 + e1);
            sp0[row0 + i] = e0 * inv;
            sp1[row0 + i] = e1 * inv;
        }
    }
    __syncthreads();

    // phase 2: block softmax stats over SCHUNK=256 scores
    float lm = gsc[tid];
    #pragma unroll
    for (int o = 16; o; o >>= 1) lm = fmaxf(lm, __shfl_xor_sync(~0u, lm, o));
    if (lane == 0) red[w] = lm;
    __syncthreads();
    float bmax = red[0];
    #pragma unroll
    for (int ww = 1; ww < 8; ww++) bmax = fmaxf(bmax, red[ww]);
    __syncthreads();

    float e0 = expf(gsc[tid] - bmax);
    gsc[tid] = e0;
    float ls = e0;
    #pragma unroll
    for (int o = 16; o; o >>= 1) ls += __shfl_xor_sync(~0u, ls, o);
    if (lane == 0) red[w] = ls;
    __syncthreads();
    float bsum = 0.f;
    #pragma unroll
    for (int ww = 0; ww < 8; ww++) bsum += red[ww];

    // phase 3: V pass — local output + global V accumulation
    float a0 = 0.f, a1 = 0.f;
    #pragma unroll 2
    for (int i = 0; i < RPW; i++) {
        const int s = s0 + i;
        const size_t bs = ((size_t)b * S + s) * H + (size_t)h * D;
        float2 v2 = __half22float2(((const __half2*)(g_v + bs))[lane]);
        float pe = gsc[row0 + i];
        a0 = fmaf(pe, v2.x, a0);
        a1 = fmaf(pe, v2.y, a1);
        if (s != 0) {
            float p0 = sp0[row0 + i];
            float p1 = sp1[row0 + i];
            float2 o2 = make_float2(p0 * v2.x + p1 * v00,
                                    p0 * v2.y + p1 * v01);
            ((float2*)(out + bs))[lane] = o2;
            if (lane == 0) {
                size_t li = CTX_ELEMS + ((size_t)bh * (S - 1) + (s - 1)) * 2;
                out[li]     = p0;
                out[li + 1] = p1;
            }
        }
    }
    vwarp[w][2 * lane]     = a0;
    vwarp[w][2 * lane + 1] = a1;
    __syncthreads();

    if (tid < D) {
        float vs = 0.f;
        #pragma unroll
        for (int ww = 0; ww < 8; ww++) vs += vwarp[ww][tid];
        g_pvac[bh][ch][tid] = vs;
    }
    if (tid == 0) {
        g_pmax[bh][ch] = bmax;
        g_psum[bh][ch] = bsum;
    }
}

__global__ __launch_bounds__(64) void gattn_combine(float* __restrict__ out)
{
    const int bh = blockIdx.x;
    const int b  = bh / NH;
    const int h  = bh % NH;
    const int tid = threadIdx.x;

    float M = -INFINITY;
    #pragma unroll
    for (int c = 0; c < GCH; c++) M = fmaxf(M, g_pmax[bh][c]);
    float denom = 0.f, vs = 0.f;
    #pragma unroll
    for (int c = 0; c < GCH; c++) {
        float sc = expf(g_pmax[bh][c] - M);
        denom += g_psum[bh][c] * sc;
        vs    += g_pvac[bh][c][tid] * sc;
    }
    out[((size_t)b * S) * H + h * D + tid] = vs / denom;
}

// ---------------------------------------------------------------------------
extern "C" void kernel_launch(void* const* d_in, const int* in_sizes, int n_in,
                              void* d_out, int out_size)
{
    const float* hidden = (const float*)d_in[0];
    const float* mask   = (const float*)d_in[1];
    const float* Wq     = (const float*)d_in[2];
    const float* bq     = (const float*)d_in[3];
    const float* Wk     = (const float*)d_in[4];
    const float* bk     = (const float*)d_in[5];
    const float* Wv     = (const float*)d_in[6];
    const float* bv     = (const float*)d_in[7];
    float* out = (float*)d_out;

    split_all<<<(TOTN16 + 255) / 256, 256>>>(hidden, Wq, Wk, Wv);

    cudaFuncSetAttribute(qkv_gemm_mma, cudaFuncAttributeMaxDynamicSharedMemorySize, GSMEM);
    dim3 ggrid(GN / TN, GM / TM, 3);   // (8, 64, 3) = 1536 CTAs
    qkv_gemm_mma<<<ggrid, 256, GSMEM>>>(bq, bk, bv);

    dim3 agrid(GCH, B * NH);
    gl_attn<<<agrid, 256>>>(mask, out);
    gattn_combine<<<B * NH, 64>>>(out);
}

// round 15
// speedup vs baseline: 1.0286x; 1.0103x over previous
#include <cuda_runtime.h>
#include <cuda_fp16.h>
#include <math.h>
#include <cstdint>

// ---------------------------------------------------------------------------
// Problem constants
// ---------------------------------------------------------------------------
#define B  4
#define S  4096
#define H  1024
#define NH 16
#define D  64
#define SCALE 0.125f

#define GM (B*S)   // 16384
#define GN H       // 1024
#define GK H       // 1024

#define CTX_ELEMS ((size_t)B * S * H)

// ---------------------------------------------------------------------------
// Device scratch (allocation-free)
// ---------------------------------------------------------------------------
__device__ __half g_q[B * S * H];
__device__ __half g_k[B * S * H];
__device__ __half g_v[B * S * H];

__device__ __half g_ah[(size_t)GM * GK];
__device__ __half g_wh[3][(size_t)GN * GK];

#define GCH 16
__device__ float g_pmax[B * NH][GCH];
__device__ float g_psum[B * NH][GCH];
__device__ float g_pvac[B * NH][GCH][D];

// ---------------------------------------------------------------------------
// Helpers
// ---------------------------------------------------------------------------
__device__ __forceinline__ uint32_t smem_u32(const void* p) {
    uint32_t a;
    asm("{ .reg .u64 t; cvta.to.shared.u64 t, %1; cvt.u32.u64 %0, t; }"
        : "=r"(a) : "l"(p));
    return a;
}

__device__ __forceinline__ void cp16(uint32_t dst, const void* src) {
    asm volatile("cp.async.cg.shared.global [%0], [%1], 16;"
                 :: "r"(dst), "l"(src));
}
#define CP_COMMIT() asm volatile("cp.async.commit_group;" ::: "memory")
#define CP_WAIT0()  asm volatile("cp.async.wait_group 0;" ::: "memory")

__device__ __forceinline__ void ldsm4(uint32_t* r, uint32_t addr) {
    asm volatile("ldmatrix.sync.aligned.m8n8.x4.shared.b16 {%0,%1,%2,%3}, [%4];"
                 : "=r"(r[0]), "=r"(r[1]), "=r"(r[2]), "=r"(r[3]) : "r"(addr));
}

__device__ __forceinline__ void mma16816h(float* c, const uint32_t* a,
                                          uint32_t b0, uint32_t b1) {
    asm volatile(
        "mma.sync.aligned.m16n8k16.row.col.f32.f16.f16.f32 "
        "{%0,%1,%2,%3}, {%4,%5,%6,%7}, {%8,%9}, {%0,%1,%2,%3};"
        : "+f"(c[0]), "+f"(c[1]), "+f"(c[2]), "+f"(c[3])
        : "r"(a[0]), "r"(a[1]), "r"(a[2]), "r"(a[3]), "r"(b0), "r"(b1));
}

// ---------------------------------------------------------------------------
// Unified convert: hidden + Wq/Wk/Wv -> fp16 (8 floats/thread, R10 shape).
// ---------------------------------------------------------------------------
#define HN8 ((GM * GK) / 8)
#define WN8 ((GN * GK) / 8)
#define TOTN8 (HN8 + 3 * WN8)

__global__ __launch_bounds__(256) void split_all(
    const float* __restrict__ hidden,
    const float* __restrict__ Wq,
    const float* __restrict__ Wk,
    const float* __restrict__ Wv)
{
    int i = blockIdx.x * blockDim.x + threadIdx.x;
    if (i >= TOTN8) return;

    const float* src;
    __half* dst;
    size_t off;
    if (i < HN8) {
        src = hidden; dst = g_ah; off = (size_t)i * 8;
    } else {
        int j0 = i - HN8;
        int w = j0 / WN8;
        off = (size_t)(j0 - w * WN8) * 8;
        src = (w == 0) ? Wq : (w == 1) ? Wk : Wv;
        dst = g_wh[w];
    }

    const float4* xp = (const float4*)(src + off);
    float4 a = xp[0], b = xp[1];
    float f[8] = {a.x, a.y, a.z, a.w, b.x, b.y, b.z, b.w};
    __align__(16) __half h[8];
    #pragma unroll
    for (int j = 0; j < 8; j++) h[j] = __float2half_rn(f[j]);
    *(uint4*)(dst + off) = *(uint4*)h;
}

// ---------------------------------------------------------------------------
// QKV GEMM via mma.sync fp16, fp32 accum, fp16 output.  (R10 champion)
// Block tile 256(M) x 128(N), K-chunk 128, 2-stage, ONE sync per chunk.
// ---------------------------------------------------------------------------
#define TM 256
#define TN 128
#define TKC 128
#define NCHUNK (GK / TKC)                  // 8
#define AT_B  (TM * 64 * 2)
#define BT_B  (TN * 64 * 2)
#define OFF_A0 0
#define OFF_A1 AT_B
#define OFF_B0 (2 * AT_B)
#define OFF_B1 (2 * AT_B + BT_B)
#define STAGE_B (2 * AT_B + 2 * BT_B)      // 98304
#define GSMEM  (2 * STAGE_B)               // 196608

__global__ __launch_bounds__(256, 1) void qkv_gemm_mma(
    const float* __restrict__ bias_q,
    const float* __restrict__ bias_k,
    const float* __restrict__ bias_v)
{
    extern __shared__ __align__(1024) char sb[];

    const int z  = blockIdx.z;
    const int bm = blockIdx.y * TM;
    const int bn = blockIdx.x * TN;

    const __half* Ah = g_ah;
    const __half* Bh = g_wh[z];
    const float* bias = (z == 0) ? bias_q : (z == 1) ? bias_k : bias_v;
    __half* Cout = (z == 0) ? g_q : (z == 1) ? g_k : g_v;

    const int tid  = threadIdx.x;
    const int wid  = tid >> 5;
    const int lane = tid & 31;
    const int wm   = (wid >> 1) * 64;
    const int wn   = (wid & 1) * 64;

    const uint32_t sbase = smem_u32(sb);

    auto load_chunk = [&](int c, int buf) {
        const int kc = c * TKC;
        const uint32_t stage = sbase + buf * STAGE_B;
        #pragma unroll
        for (int sub = 0; sub < 2; sub++) {
            uint32_t dtile = stage + (sub ? OFF_A1 : OFF_A0);
            const int kb = kc + sub * 64;
            #pragma unroll
            for (int i = 0; i < 8; i++) {
                int idx = tid + i * 256;
                int row = idx >> 3;
                int v   = idx & 7;
                uint32_t off = (uint32_t)(row << 7) + (uint32_t)(v << 4);
                off ^= ((uint32_t)(row & 7) << 4);
                cp16(dtile + off, Ah + (size_t)(bm + row) * GK + kb + v * 8);
            }
        }
        #pragma unroll
        for (int sub = 0; sub < 2; sub++) {
            uint32_t dtile = stage + (sub ? OFF_B1 : OFF_B0);
            const int kb = kc + sub * 64;
            #pragma unroll
            for (int i = 0; i < 4; i++) {
                int idx = tid + i * 256;
                int row = idx >> 3;
                int v   = idx & 7;
                uint32_t off = (uint32_t)(row << 7) + (uint32_t)(v << 4);
                off ^= ((uint32_t)(row & 7) << 4);
                cp16(dtile + off, Bh + (size_t)(bn + row) * GK + kb + v * 8);
            }
        }
    };

    float acc[4][8][4];
    #pragma unroll
    for (int f = 0; f < 4; f++)
        #pragma unroll
        for (int g = 0; g < 8; g++)
            #pragma unroll
            for (int j = 0; j < 4; j++) acc[f][g][j] = 0.f;

    const int a_row_l = lane & 15;
    const int a_kb_l  = (lane >> 4) << 4;
    const int b_row_l = (lane & 7) + ((lane >> 4) << 3);
    const int b_kb_l  = ((lane >> 3) & 1) << 4;

    load_chunk(0, 0);
    CP_COMMIT();

    for (int c = 0; c < NCHUNK; c++) {
        const int buf = c & 1;
        CP_WAIT0();
        __syncthreads();
        if (c + 1 < NCHUNK) {
            load_chunk(c + 1, buf ^ 1);
            CP_COMMIT();
        }

        const uint32_t stage = sbase + buf * STAGE_B;

        #pragma unroll
        for (int sub = 0; sub < 2; sub++) {
            const uint32_t baseA = stage + (sub ? OFF_A1 : OFF_A0);
            const uint32_t baseB = stage + (sub ? OFF_B1 : OFF_B0);
            #pragma unroll
            for (int s = 0; s < 4; s++) {
                uint32_t aF[4][4], bH[4][4];
                const uint32_t cbA = (uint32_t)(s * 32 + a_kb_l);
                const uint32_t cbB = (uint32_t)(s * 32 + b_kb_l);
                #pragma unroll
                for (int f = 0; f < 4; f++) {
                    int row = wm + f * 16 + a_row_l;
                    uint32_t off = (uint32_t)(row << 7) + (cbA ^ ((uint32_t)(row & 7) << 4));
                    ldsm4(aF[f], baseA + off);
                }
                #pragma unroll
                for (int g16 = 0; g16 < 4; g16++) {
                    int row = wn + g16 * 16 + b_row_l;
                    uint32_t off = (uint32_t)(row << 7) + (cbB ^ ((uint32_t)(row & 7) << 4));
                    ldsm4(bH[g16], baseB + off);
                }
                #pragma unroll
                for (int f = 0; f < 4; f++) {
                    #pragma unroll
                    for (int g16 = 0; g16 < 4; g16++) {
                        #pragma unroll
                        for (int p = 0; p < 2; p++) {
                            float* cc = acc[f][g16 * 2 + p];
                            mma16816h(cc, aF[f], bH[g16][2*p], bH[g16][2*p+1]);
                        }
                    }
                }
            }
        }
    }

    // ---- epilogue: bias + fp16 store ----
    #pragma unroll
    for (int f = 0; f < 4; f++) {
        #pragma unroll
        for (int g = 0; g < 8; g++) {
            int row = bm + wm + f * 16 + (lane >> 2);
            int col = bn + wn + g * 8 + (lane & 3) * 2;
            float b0 = bias[col], b1 = bias[col + 1];
            __half2 h0 = __floats2half2_rn(acc[f][g][0] + b0, acc[f][g][1] + b1);
            __half2 h1 = __floats2half2_rn(acc[f][g][2] + b0, acc[f][g][3] + b1);
            *(__half2*)(Cout + (size_t)row * GN + col)       = h0;
            *(__half2*)(Cout + (size_t)(row + 8) * GN + col) = h1;
        }
    }
}

// ---------------------------------------------------------------------------
// Fused attention (two-pass, R10 champion): grid (GCH, B*NH), block 256.
// ---------------------------------------------------------------------------
#define SCHUNK (S / GCH)   // 256
#define RPW (SCHUNK / 8)   // 32 rows per warp

__global__ __launch_bounds__(256) void gl_attn(
    const float* __restrict__ mask, float* __restrict__ out)
{
    const int ch = blockIdx.x;
    const int bh = blockIdx.y;
    const int b  = bh / NH;
    const int h  = bh % NH;

    __shared__ float sq0[D], sk0[D], sv0[D];
    __shared__ float gsc[SCHUNK];
    __shared__ float sp0[SCHUNK], sp1[SCHUNK];
    __shared__ float red[8];
    __shared__ float vwarp[8][D];

    const int tid  = threadIdx.x;
    const int lane = tid & 31;
    const int w    = tid >> 5;

    const size_t base0 = ((size_t)b * S) * H + (size_t)h * D;
    if (tid < D) {
        sq0[tid] = __half2float(g_q[base0 + tid]);
        sk0[tid] = __half2float(g_k[base0 + tid]);
        sv0[tid] = __half2float(g_v[base0 + tid]);
    }
    __syncthreads();

    const float q00 = sq0[2 * lane], q01 = sq0[2 * lane + 1];
    const float k00 = sk0[2 * lane], k01 = sk0[2 * lane + 1];
    const float v00 = sv0[2 * lane], v01 = sv0[2 * lane + 1];

    const int row0 = w * RPW;
    const int s0   = ch * SCHUNK + row0;

    // phase 1: scores (global + local 2-way softmax)
    #pragma unroll 2
    for (int i = 0; i < RPW; i++) {
        const int s = s0 + i;
        const size_t bs = ((size_t)b * S + s) * H + (size_t)h * D;
        float2 q2 = __half22float2(((const __half2*)(g_q + bs))[lane]);
        float2 k2 = __half22float2(((const __half2*)(g_k + bs))[lane]);

        float dg = q00 * k2.x + q01 * k2.y;
        float ds = q2.x * k2.x + q2.y * k2.y;
        float dl = q2.x * k00 + q2.y * k01;
        #pragma unroll
        for (int o = 16; o; o >>= 1) {
            dg += __shfl_xor_sync(~0u, dg, o);
            ds += __shfl_xor_sync(~0u, ds, o);
            dl += __shfl_xor_sync(~0u, dl, o);
        }
        if (lane == 0) {
            gsc[row0 + i] = dg * SCALE + mask[(size_t)b * S + s];
            float ps = ds * SCALE, pg = dl * SCALE;
            float m  = fmaxf(ps, pg);
            float e0 = expf(ps - m), e1 = expf(pg - m);
            float inv = 1.f / (e0 + e1);
            sp0[row0 + i] = e0 * inv;
            sp1[row0 + i] = e1 * inv;
        }
    }
    __syncthreads();

    // phase 2: block softmax stats over SCHUNK=256 scores
    float lm = gsc[tid];
    #pragma unroll
    for (int o = 16; o; o >>= 1) lm = fmaxf(lm, __shfl_xor_sync(~0u, lm, o));
    if (lane == 0) red[w] = lm;
    __syncthreads();
    float bmax = red[0];
    #pragma unroll
    for (int ww = 1; ww < 8; ww++) bmax = fmaxf(bmax, red[ww]);
    __syncthreads();

    float e0 = expf(gsc[tid] - bmax);
    gsc[tid] = e0;
    float ls = e0;
    #pragma unroll
    for (int o = 16; o; o >>= 1) ls += __shfl_xor_sync(~0u, ls, o);
    if (lane == 0) red[w] = ls;
    __syncthreads();
    float bsum = 0.f;
    #pragma unroll
    for (int ww = 0; ww < 8; ww++) bsum += red[ww];

    // phase 3: V pass — local output + global V accumulation
    float a0 = 0.f, a1 = 0.f;
    #pragma unroll 2
    for (int i = 0; i < RPW; i++) {
        const int s = s0 + i;
        const size_t bs = ((size_t)b * S + s) * H + (size_t)h * D;
        float2 v2 = __half22float2(((const __half2*)(g_v + bs))[lane]);
        float pe = gsc[row0 + i];
        a0 = fmaf(pe, v2.x, a0);
        a1 = fmaf(pe, v2.y, a1);
        if (s != 0) {
            float p0 = sp0[row0 + i];
            float p1 = sp1[row0 + i];
            float2 o2 = make_float2(p0 * v2.x + p1 * v00,
                                    p0 * v2.y + p1 * v01);
            ((float2*)(out + bs))[lane] = o2;
            if (lane == 0) {
                size_t li = CTX_ELEMS + ((size_t)bh * (S - 1) + (s - 1)) * 2;
                out[li]     = p0;
                out[li + 1] = p1;
            }
        }
    }
    vwarp[w][2 * lane]     = a0;
    vwarp[w][2 * lane + 1] = a1;
    __syncthreads();

    if (tid < D) {
        float vs = 0.f;
        #pragma unroll
        for (int ww = 0; ww < 8; ww++) vs += vwarp[ww][tid];
        g_pvac[bh][ch][tid] = vs;
    }
    if (tid == 0) {
        g_pmax[bh][ch] = bmax;
        g_psum[bh][ch] = bsum;
    }
}

__global__ __launch_bounds__(64) void gattn_combine(float* __restrict__ out)
{
    const int bh = blockIdx.x;
    const int b  = bh / NH;
    const int h  = bh % NH;
    const int tid = threadIdx.x;

    float M = -INFINITY;
    #pragma unroll
    for (int c = 0; c < GCH; c++) M = fmaxf(M, g_pmax[bh][c]);
    float denom = 0.f, vs = 0.f;
    #pragma unroll
    for (int c = 0; c < GCH; c++) {
        float sc = expf(g_pmax[bh][c] - M);
        denom += g_psum[bh][c] * sc;
        vs    += g_pvac[bh][c][tid] * sc;
    }
    out[((size_t)b * S) * H + h * D + tid] = vs / denom;
}

// ---------------------------------------------------------------------------
extern "C" void kernel_launch(void* const* d_in, const int* in_sizes, int n_in,
                              void* d_out, int out_size)
{
    const float* hidden = (const float*)d_in[0];
    const float* mask   = (const float*)d_in[1];
    const float* Wq     = (const float*)d_in[2];
    const float* bq     = (const float*)d_in[3];
    const float* Wk     = (const float*)d_in[4];
    const float* bk     = (const float*)d_in[5];
    const float* Wv     = (const float*)d_in[6];
    const float* bv     = (const float*)d_in[7];
    float* out = (float*)d_out;

    split_all<<<(TOTN8 + 255) / 256, 256>>>(hidden, Wq, Wk, Wv);

    cudaFuncSetAttribute(qkv_gemm_mma, cudaFuncAttributeMaxDynamicSharedMemorySize, GSMEM);
    dim3 ggrid(GN / TN, GM / TM, 3);   // (8, 64, 3) = 1536 CTAs
    qkv_gemm_mma<<<ggrid, 256, GSMEM>>>(bq, bk, bv);

    dim3 agrid(GCH, B * NH);
    gl_attn<<<agrid, 256>>>(mask, out);
    gattn_combine<<<B * NH, 64>>>(out);
}

// round 16
// speedup vs baseline: 1.0287x; 1.0001x over previous
#include <cuda_runtime.h>
#include <cuda_fp16.h>
#include <math.h>
#include <cstdint>

// ---------------------------------------------------------------------------
// Problem constants
// ---------------------------------------------------------------------------
#define B  4
#define S  4096
#define H  1024
#define NH 16
#define D  64
#define SCALE 0.125f

#define GM (B*S)   // 16384
#define GN H       // 1024
#define GK H       // 1024

#define CTX_ELEMS ((size_t)B * S * H)

// ---------------------------------------------------------------------------
// Device scratch (allocation-free)
// ---------------------------------------------------------------------------
__device__ __half g_q[B * S * H];
__device__ __half g_k[B * S * H];
__device__ __half g_v[B * S * H];

__device__ __half g_ah[(size_t)GM * GK];
__device__ __half g_wh[3][(size_t)GN * GK];

#define GCH 16
__device__ float g_pmax[B * NH][GCH];
__device__ float g_psum[B * NH][GCH];
__device__ float g_pvac[B * NH][GCH][D];

// ---------------------------------------------------------------------------
// Helpers
// ---------------------------------------------------------------------------
__device__ __forceinline__ uint32_t smem_u32(const void* p) {
    uint32_t a;
    asm("{ .reg .u64 t; cvta.to.shared.u64 t, %1; cvt.u32.u64 %0, t; }"
        : "=r"(a) : "l"(p));
    return a;
}

__device__ __forceinline__ void cp16(uint32_t dst, const void* src) {
    asm volatile("cp.async.cg.shared.global [%0], [%1], 16;"
                 :: "r"(dst), "l"(src));
}
#define CP_COMMIT() asm volatile("cp.async.commit_group;" ::: "memory")
#define CP_WAIT0()  asm volatile("cp.async.wait_group 0;" ::: "memory")

__device__ __forceinline__ void ldsm4(uint32_t* r, uint32_t addr) {
    asm volatile("ldmatrix.sync.aligned.m8n8.x4.shared.b16 {%0,%1,%2,%3}, [%4];"
                 : "=r"(r[0]), "=r"(r[1]), "=r"(r[2]), "=r"(r[3]) : "r"(addr));
}

__device__ __forceinline__ void mma16816h(float* c, const uint32_t* a,
                                          uint32_t b0, uint32_t b1) {
    asm volatile(
        "mma.sync.aligned.m16n8k16.row.col.f32.f16.f16.f32 "
        "{%0,%1,%2,%3}, {%4,%5,%6,%7}, {%8,%9}, {%0,%1,%2,%3};"
        : "+f"(c[0]), "+f"(c[1]), "+f"(c[2]), "+f"(c[3])
        : "r"(a[0]), "r"(a[1]), "r"(a[2]), "r"(a[3]), "r"(b0), "r"(b1));
}

// ---------------------------------------------------------------------------
// Unified convert: hidden + Wq/Wk/Wv -> fp16 (8 floats/thread).
// ---------------------------------------------------------------------------
#define HN8 ((GM * GK) / 8)
#define WN8 ((GN * GK) / 8)
#define TOTN8 (HN8 + 3 * WN8)

__global__ __launch_bounds__(256) void split_all(
    const float* __restrict__ hidden,
    const float* __restrict__ Wq,
    const float* __restrict__ Wk,
    const float* __restrict__ Wv)
{
    int i = blockIdx.x * blockDim.x + threadIdx.x;
    if (i >= TOTN8) return;

    const float* src;
    __half* dst;
    size_t off;
    if (i < HN8) {
        src = hidden; dst = g_ah; off = (size_t)i * 8;
    } else {
        int j0 = i - HN8;
        int w = j0 / WN8;
        off = (size_t)(j0 - w * WN8) * 8;
        src = (w == 0) ? Wq : (w == 1) ? Wk : Wv;
        dst = g_wh[w];
    }

    const float4* xp = (const float4*)(src + off);
    float4 a = xp[0], b = xp[1];
    float f[8] = {a.x, a.y, a.z, a.w, b.x, b.y, b.z, b.w};
    __align__(16) __half h[8];
    #pragma unroll
    for (int j = 0; j < 8; j++) h[j] = __float2half_rn(f[j]);
    *(uint4*)(dst + off) = *(uint4*)h;
}

// ---------------------------------------------------------------------------
// QKV GEMM via mma.sync fp16, fp32 accum, fp16 output.  (champion)
// Block tile 256(M) x 128(N), K-chunk 128, 2-stage, ONE sync per chunk.
// ---------------------------------------------------------------------------
#define TM 256
#define TN 128
#define TKC 128
#define NCHUNK (GK / TKC)                  // 8
#define AT_B  (TM * 64 * 2)
#define BT_B  (TN * 64 * 2)
#define OFF_A0 0
#define OFF_A1 AT_B
#define OFF_B0 (2 * AT_B)
#define OFF_B1 (2 * AT_B + BT_B)
#define STAGE_B (2 * AT_B + 2 * BT_B)      // 98304
#define GSMEM  (2 * STAGE_B)               // 196608

__global__ __launch_bounds__(256, 1) void qkv_gemm_mma(
    const float* __restrict__ bias_q,
    const float* __restrict__ bias_k,
    const float* __restrict__ bias_v)
{
    extern __shared__ __align__(1024) char sb[];

    const int z  = blockIdx.z;
    const int bm = blockIdx.y * TM;
    const int bn = blockIdx.x * TN;

    const __half* Ah = g_ah;
    const __half* Bh = g_wh[z];
    const float* bias = (z == 0) ? bias_q : (z == 1) ? bias_k : bias_v;
    __half* Cout = (z == 0) ? g_q : (z == 1) ? g_k : g_v;

    const int tid  = threadIdx.x;
    const int wid  = tid >> 5;
    const int lane = tid & 31;
    const int wm   = (wid >> 1) * 64;
    const int wn   = (wid & 1) * 64;

    const uint32_t sbase = smem_u32(sb);

    auto load_chunk = [&](int c, int buf) {
        const int kc = c * TKC;
        const uint32_t stage = sbase + buf * STAGE_B;
        #pragma unroll
        for (int sub = 0; sub < 2; sub++) {
            uint32_t dtile = stage + (sub ? OFF_A1 : OFF_A0);
            const int kb = kc + sub * 64;
            #pragma unroll
            for (int i = 0; i < 8; i++) {
                int idx = tid + i * 256;
                int row = idx >> 3;
                int v   = idx & 7;
                uint32_t off = (uint32_t)(row << 7) + (uint32_t)(v << 4);
                off ^= ((uint32_t)(row & 7) << 4);
                cp16(dtile + off, Ah + (size_t)(bm + row) * GK + kb + v * 8);
            }
        }
        #pragma unroll
        for (int sub = 0; sub < 2; sub++) {
            uint32_t dtile = stage + (sub ? OFF_B1 : OFF_B0);
            const int kb = kc + sub * 64;
            #pragma unroll
            for (int i = 0; i < 4; i++) {
                int idx = tid + i * 256;
                int row = idx >> 3;
                int v   = idx & 7;
                uint32_t off = (uint32_t)(row << 7) + (uint32_t)(v << 4);
                off ^= ((uint32_t)(row & 7) << 4);
                cp16(dtile + off, Bh + (size_t)(bn + row) * GK + kb + v * 8);
            }
        }
    };

    float acc[4][8][4];
    #pragma unroll
    for (int f = 0; f < 4; f++)
        #pragma unroll
        for (int g = 0; g < 8; g++)
            #pragma unroll
            for (int j = 0; j < 4; j++) acc[f][g][j] = 0.f;

    const int a_row_l = lane & 15;
    const int a_kb_l  = (lane >> 4) << 4;
    const int b_row_l = (lane & 7) + ((lane >> 4) << 3);
    const int b_kb_l  = ((lane >> 3) & 1) << 4;

    load_chunk(0, 0);
    CP_COMMIT();

    for (int c = 0; c < NCHUNK; c++) {
        const int buf = c & 1;
        CP_WAIT0();
        __syncthreads();
        if (c + 1 < NCHUNK) {
            load_chunk(c + 1, buf ^ 1);
            CP_COMMIT();
        }

        const uint32_t stage = sbase + buf * STAGE_B;

        #pragma unroll
        for (int sub = 0; sub < 2; sub++) {
            const uint32_t baseA = stage + (sub ? OFF_A1 : OFF_A0);
            const uint32_t baseB = stage + (sub ? OFF_B1 : OFF_B0);
            #pragma unroll
            for (int s = 0; s < 4; s++) {
                uint32_t aF[4][4], bH[4][4];
                const uint32_t cbA = (uint32_t)(s * 32 + a_kb_l);
                const uint32_t cbB = (uint32_t)(s * 32 + b_kb_l);
                #pragma unroll
                for (int f = 0; f < 4; f++) {
                    int row = wm + f * 16 + a_row_l;
                    uint32_t off = (uint32_t)(row << 7) + (cbA ^ ((uint32_t)(row & 7) << 4));
                    ldsm4(aF[f], baseA + off);
                }
                #pragma unroll
                for (int g16 = 0; g16 < 4; g16++) {
                    int row = wn + g16 * 16 + b_row_l;
                    uint32_t off = (uint32_t)(row << 7) + (cbB ^ ((uint32_t)(row & 7) << 4));
                    ldsm4(bH[g16], baseB + off);
                }
                #pragma unroll
                for (int f = 0; f < 4; f++) {
                    #pragma unroll
                    for (int g16 = 0; g16 < 4; g16++) {
                        #pragma unroll
                        for (int p = 0; p < 2; p++) {
                            float* cc = acc[f][g16 * 2 + p];
                            mma16816h(cc, aF[f], bH[g16][2*p], bH[g16][2*p+1]);
                        }
                    }
                }
            }
        }
    }

    // ---- epilogue: bias + fp16 store ----
    #pragma unroll
    for (int f = 0; f < 4; f++) {
        #pragma unroll
        for (int g = 0; g < 8; g++) {
            int row = bm + wm + f * 16 + (lane >> 2);
            int col = bn + wn + g * 8 + (lane & 3) * 2;
            float b0 = bias[col], b1 = bias[col + 1];
            __half2 h0 = __floats2half2_rn(acc[f][g][0] + b0, acc[f][g][1] + b1);
            __half2 h1 = __floats2half2_rn(acc[f][g][2] + b0, acc[f][g][3] + b1);
            *(__half2*)(Cout + (size_t)row * GN + col)       = h0;
            *(__half2*)(Cout + (size_t)(row + 8) * GN + col) = h1;
        }
    }
}

// ---------------------------------------------------------------------------
// Fused attention (two-pass, champion): grid (GCH, B*NH), block 256.
// ---------------------------------------------------------------------------
#define SCHUNK (S / GCH)   // 256
#define RPW (SCHUNK / 8)   // 32 rows per warp

__global__ __launch_bounds__(256) void gl_attn(
    const float* __restrict__ mask, float* __restrict__ out)
{
    const int ch = blockIdx.x;
    const int bh = blockIdx.y;
    const int b  = bh / NH;
    const int h  = bh % NH;

    __shared__ float sq0[D], sk0[D], sv0[D];
    __shared__ float gsc[SCHUNK];
    __shared__ float sp0[SCHUNK], sp1[SCHUNK];
    __shared__ float red[8];
    __shared__ float vwarp[8][D];

    const int tid  = threadIdx.x;
    const int lane = tid & 31;
    const int w    = tid >> 5;

    const size_t base0 = ((size_t)b * S) * H + (size_t)h * D;
    if (tid < D) {
        sq0[tid] = __half2float(g_q[base0 + tid]);
        sk0[tid] = __half2float(g_k[base0 + tid]);
        sv0[tid] = __half2float(g_v[base0 + tid]);
    }
    __syncthreads();

    const float q00 = sq0[2 * lane], q01 = sq0[2 * lane + 1];
    const float k00 = sk0[2 * lane], k01 = sk0[2 * lane + 1];
    const float v00 = sv0[2 * lane], v01 = sv0[2 * lane + 1];

    const int row0 = w * RPW;
    const int s0   = ch * SCHUNK + row0;

    // phase 1: scores (global + local 2-way softmax)
    #pragma unroll 2
    for (int i = 0; i < RPW; i++) {
        const int s = s0 + i;
        const size_t bs = ((size_t)b * S + s) * H + (size_t)h * D;
        float2 q2 = __half22float2(((const __half2*)(g_q + bs))[lane]);
        float2 k2 = __half22float2(((const __half2*)(g_k + bs))[lane]);

        float dg = q00 * k2.x + q01 * k2.y;
        float ds = q2.x * k2.x + q2.y * k2.y;
        float dl = q2.x * k00 + q2.y * k01;
        #pragma unroll
        for (int o = 16; o; o >>= 1) {
            dg += __shfl_xor_sync(~0u, dg, o);
            ds += __shfl_xor_sync(~0u, ds, o);
            dl += __shfl_xor_sync(~0u, dl, o);
        }
        if (lane == 0) {
            gsc[row0 + i] = dg * SCALE + mask[(size_t)b * S + s];
            float ps = ds * SCALE, pg = dl * SCALE;
            float m  = fmaxf(ps, pg);
            float e0 = expf(ps - m), e1 = expf(pg - m);
            float inv = 1.f / (e0 + e1);
            sp0[row0 + i] = e0 * inv;
            sp1[row0 + i] = e1 * inv;
        }
    }
    __syncthreads();

    // phase 2: block softmax stats over SCHUNK=256 scores
    float lm = gsc[tid];
    #pragma unroll
    for (int o = 16; o; o >>= 1) lm = fmaxf(lm, __shfl_xor_sync(~0u, lm, o));
    if (lane == 0) red[w] = lm;
    __syncthreads();
    float bmax = red[0];
    #pragma unroll
    for (int ww = 1; ww < 8; ww++) bmax = fmaxf(bmax, red[ww]);
    __syncthreads();

    float e0 = expf(gsc[tid] - bmax);
    gsc[tid] = e0;
    float ls = e0;
    #pragma unroll
    for (int o = 16; o; o >>= 1) ls += __shfl_xor_sync(~0u, ls, o);
    if (lane == 0) red[w] = ls;
    __syncthreads();
    float bsum = 0.f;
    #pragma unroll
    for (int ww = 0; ww < 8; ww++) bsum += red[ww];

    // phase 3: V pass — local output + global V accumulation
    float a0 = 0.f, a1 = 0.f;
    #pragma unroll 2
    for (int i = 0; i < RPW; i++) {
        const int s = s0 + i;
        const size_t bs = ((size_t)b * S + s) * H + (size_t)h * D;
        float2 v2 = __half22float2(((const __half2*)(g_v + bs))[lane]);
        float pe = gsc[row0 + i];
        a0 = fmaf(pe, v2.x, a0);
        a1 = fmaf(pe, v2.y, a1);
        if (s != 0) {
            float p0 = sp0[row0 + i];
            float p1 = sp1[row0 + i];
            float2 o2 = make_float2(p0 * v2.x + p1 * v00,
                                    p0 * v2.y + p1 * v01);
            ((float2*)(out + bs))[lane] = o2;
            if (lane == 0) {
                size_t li = CTX_ELEMS + ((size_t)bh * (S - 1) + (s - 1)) * 2;
                out[li]     = p0;
                out[li + 1] = p1;
            }
        }
    }
    vwarp[w][2 * lane]     = a0;
    vwarp[w][2 * lane + 1] = a1;
    __syncthreads();

    if (tid < D) {
        float vs = 0.f;
        #pragma unroll
        for (int ww = 0; ww < 8; ww++) vs += vwarp[ww][tid];
        g_pvac[bh][ch][tid] = vs;
    }
    if (tid == 0) {
        g_pmax[bh][ch] = bmax;
        g_psum[bh][ch] = bsum;
    }
}

__global__ __launch_bounds__(64) void gattn_combine(float* __restrict__ out)
{
    const int bh = blockIdx.x;
    const int b  = bh / NH;
    const int h  = bh % NH;
    const int tid = threadIdx.x;

    float M = -INFINITY;
    #pragma unroll
    for (int c = 0; c < GCH; c++) M = fmaxf(M, g_pmax[bh][c]);
    float denom = 0.f, vs = 0.f;
    #pragma unroll
    for (int c = 0; c < GCH; c++) {
        float sc = expf(g_pmax[bh][c] - M);
        denom += g_psum[bh][c] * sc;
        vs    += g_pvac[bh][c][tid] * sc;
    }
    out[((size_t)b * S) * H + h * D + tid] = vs / denom;
}

// ---------------------------------------------------------------------------
extern "C" void kernel_launch(void* const* d_in, const int* in_sizes, int n_in,
                              void* d_out, int out_size)
{
    const float* hidden = (const float*)d_in[0];
    const float* mask   = (const float*)d_in[1];
    const float* Wq     = (const float*)d_in[2];
    const float* bq     = (const float*)d_in[3];
    const float* Wk     = (const float*)d_in[4];
    const float* bk     = (const float*)d_in[5];
    const float* Wv     = (const float*)d_in[6];
    const float* bv     = (const float*)d_in[7];
    float* out = (float*)d_out;

    split_all<<<(TOTN8 + 255) / 256, 256>>>(hidden, Wq, Wk, Wv);

    cudaFuncSetAttribute(qkv_gemm_mma, cudaFuncAttributeMaxDynamicSharedMemorySize, GSMEM);
    dim3 ggrid(GN / TN, GM / TM, 3);   // (8, 64, 3) = 1536 CTAs
    qkv_gemm_mma<<<ggrid, 256, GSMEM>>>(bq, bk, bv);

    dim3 agrid(GCH, B * NH);
    gl_attn<<<agrid, 256>>>(mask, out);
    gattn_combine<<<B * NH, 64>>>(out);
}

// round 17
// speedup vs baseline: 1.1231x; 1.0918x over previous
#include <cuda_runtime.h>
#include <cuda_fp16.h>
#include <math.h>
#include <cstdint>

// ---------------------------------------------------------------------------
// Problem constants
// ---------------------------------------------------------------------------
#define B  4
#define S  4096
#define H  1024
#define NH 16
#define D  64
#define SCALE 0.125f

#define GM (B*S)   // 16384
#define GN H       // 1024
#define GK H       // 1024

#define CTX_ELEMS ((size_t)B * S * H)

// ---------------------------------------------------------------------------
// Device scratch (allocation-free)
// ---------------------------------------------------------------------------
__device__ __half g_q[B * S * H];
__device__ __half g_k[B * S * H];
__device__ __half g_v[B * S * H];

__device__ __half g_ah[(size_t)GM * GK];
__device__ __half g_wh[3][(size_t)GN * GK];

#define GCH 16
__device__ float g_pmax[B * NH][GCH];
__device__ float g_psum[B * NH][GCH];
__device__ float g_pvac[B * NH][GCH][D];

// ---------------------------------------------------------------------------
// Helpers
// ---------------------------------------------------------------------------
__device__ __forceinline__ uint32_t smem_u32(const void* p) {
    uint32_t a;
    asm("{ .reg .u64 t; cvta.to.shared.u64 t, %1; cvt.u32.u64 %0, t; }"
        : "=r"(a) : "l"(p));
    return a;
}

__device__ __forceinline__ void cp16(uint32_t dst, const void* src) {
    asm volatile("cp.async.cg.shared.global [%0], [%1], 16;"
                 :: "r"(dst), "l"(src));
}
#define CP_COMMIT() asm volatile("cp.async.commit_group;" ::: "memory")
#define CP_WAIT0()  asm volatile("cp.async.wait_group 0;" ::: "memory")

__device__ __forceinline__ void ldsm4(uint32_t* r, uint32_t addr) {
    asm volatile("ldmatrix.sync.aligned.m8n8.x4.shared.b16 {%0,%1,%2,%3}, [%4];"
                 : "=r"(r[0]), "=r"(r[1]), "=r"(r[2]), "=r"(r[3]) : "r"(addr));
}

__device__ __forceinline__ void mma16816h(float* c, const uint32_t* a,
                                          uint32_t b0, uint32_t b1) {
    asm volatile(
        "mma.sync.aligned.m16n8k16.row.col.f32.f16.f16.f32 "
        "{%0,%1,%2,%3}, {%4,%5,%6,%7}, {%8,%9}, {%0,%1,%2,%3};"
        : "+f"(c[0]), "+f"(c[1]), "+f"(c[2]), "+f"(c[3])
        : "r"(a[0]), "r"(a[1]), "r"(a[2]), "r"(a[3]), "r"(b0), "r"(b1));
}

// ---------------------------------------------------------------------------
// Unified convert: hidden + Wq/Wk/Wv -> fp16 (8 floats/thread).
// ---------------------------------------------------------------------------
#define HN8 ((GM * GK) / 8)
#define WN8 ((GN * GK) / 8)
#define TOTN8 (HN8 + 3 * WN8)

__global__ __launch_bounds__(256) void split_all(
    const float* __restrict__ hidden,
    const float* __restrict__ Wq,
    const float* __restrict__ Wk,
    const float* __restrict__ Wv)
{
    int i = blockIdx.x * blockDim.x + threadIdx.x;
    if (i >= TOTN8) return;

    const float* src;
    __half* dst;
    size_t off;
    if (i < HN8) {
        src = hidden; dst = g_ah; off = (size_t)i * 8;
    } else {
        int j0 = i - HN8;
        int w = j0 / WN8;
        off = (size_t)(j0 - w * WN8) * 8;
        src = (w == 0) ? Wq : (w == 1) ? Wk : Wv;
        dst = g_wh[w];
    }

    const float4* xp = (const float4*)(src + off);
    float4 a = xp[0], b = xp[1];
    float f[8] = {a.x, a.y, a.z, a.w, b.x, b.y, b.z, b.w};
    __align__(16) __half h[8];
    #pragma unroll
    for (int j = 0; j < 8; j++) h[j] = __float2half_rn(f[j]);
    *(uint4*)(dst + off) = *(uint4*)h;
}

// ---------------------------------------------------------------------------
// QKV GEMM via mma.sync fp16, fp32 accum, fp16 output.
// Block tile 128(M) x 128(N), K-chunk 64, 2-stage, single sync per chunk.
// 4 warps (64x64 warp tile), 64 KB smem -> 2 CTAs/SM for cross-CTA overlap.
// ---------------------------------------------------------------------------
#define TM 128
#define TN 128
#define TKC 64
#define NCHUNK (GK / TKC)                  // 16
#define AT_B  (TM * 64 * 2)                // 16384
#define BT_B  (TN * 64 * 2)                // 16384
#define OFF_A  0
#define OFF_Bt AT_B
#define STAGE_B (AT_B + BT_B)              // 32768
#define GSMEM  (2 * STAGE_B)               // 65536

__global__ __launch_bounds__(128, 2) void qkv_gemm_mma(
    const float* __restrict__ bias_q,
    const float* __restrict__ bias_k,
    const float* __restrict__ bias_v)
{
    extern __shared__ __align__(1024) char sb[];

    const int z  = blockIdx.z;
    const int bm = blockIdx.y * TM;
    const int bn = blockIdx.x * TN;

    const __half* Ah = g_ah;
    const __half* Bh = g_wh[z];
    const float* bias = (z == 0) ? bias_q : (z == 1) ? bias_k : bias_v;
    __half* Cout = (z == 0) ? g_q : (z == 1) ? g_k : g_v;

    const int tid  = threadIdx.x;         // 0..127
    const int wid  = tid >> 5;            // 0..3
    const int lane = tid & 31;
    const int wm   = (wid >> 1) * 64;     // 0,64
    const int wn   = (wid & 1) * 64;      // 0,64

    const uint32_t sbase = smem_u32(sb);

    auto load_chunk = [&](int c, int buf) {
        const int kc = c * TKC;
        const uint32_t stage = sbase + buf * STAGE_B;
        // A: 128 rows x 64 cols fp16 -> 1024 cp16, 8 per thread
        {
            uint32_t dtile = stage + OFF_A;
            #pragma unroll
            for (int i = 0; i < 8; i++) {
                int idx = tid + i * 128;
                int row = idx >> 3;
                int v   = idx & 7;
                uint32_t off = (uint32_t)(row << 7) + (uint32_t)(v << 4);
                off ^= ((uint32_t)(row & 7) << 4);
                cp16(dtile + off, Ah + (size_t)(bm + row) * GK + kc + v * 8);
            }
        }
        // B: 128 rows x 64 cols -> 8 per thread
        {
            uint32_t dtile = stage + OFF_Bt;
            #pragma unroll
            for (int i = 0; i < 8; i++) {
                int idx = tid + i * 128;
                int row = idx >> 3;
                int v   = idx & 7;
                uint32_t off = (uint32_t)(row << 7) + (uint32_t)(v << 4);
                off ^= ((uint32_t)(row & 7) << 4);
                cp16(dtile + off, Bh + (size_t)(bn + row) * GK + kc + v * 8);
            }
        }
    };

    float acc[4][8][4];
    #pragma unroll
    for (int f = 0; f < 4; f++)
        #pragma unroll
        for (int g = 0; g < 8; g++)
            #pragma unroll
            for (int j = 0; j < 4; j++) acc[f][g][j] = 0.f;

    const int a_row_l = lane & 15;
    const int a_kb_l  = (lane >> 4) << 4;
    const int b_row_l = (lane & 7) + ((lane >> 4) << 3);
    const int b_kb_l  = ((lane >> 3) & 1) << 4;

    load_chunk(0, 0);
    CP_COMMIT();

    for (int c = 0; c < NCHUNK; c++) {
        const int buf = c & 1;
        CP_WAIT0();          // chunk c landed (only group outstanding)
        __syncthreads();     // all warps done reading the other buffer
        if (c + 1 < NCHUNK) {
            load_chunk(c + 1, buf ^ 1);
            CP_COMMIT();
        }

        const uint32_t stage = sbase + buf * STAGE_B;
        const uint32_t baseA = stage + OFF_A;
        const uint32_t baseB = stage + OFF_Bt;

        #pragma unroll
        for (int s = 0; s < 4; s++) {
            uint32_t aF[4][4], bH[4][4];
            const uint32_t cbA = (uint32_t)(s * 16 + a_kb_l);
            const uint32_t cbB = (uint32_t)(s * 16 + b_kb_l);
            // NOTE: TKC=64 -> k-steps of 16 cols = 32 bytes; s covers 4 steps
            const uint32_t cA = (uint32_t)(s * 32 + a_kb_l);
            const uint32_t cB = (uint32_t)(s * 32 + b_kb_l);
            (void)cbA; (void)cbB;
            #pragma unroll
            for (int f = 0; f < 4; f++) {
                int row = wm + f * 16 + a_row_l;
                uint32_t off = (uint32_t)(row << 7) + (cA ^ ((uint32_t)(row & 7) << 4));
                ldsm4(aF[f], baseA + off);
            }
            #pragma unroll
            for (int g16 = 0; g16 < 4; g16++) {
                int row = wn + g16 * 16 + b_row_l;
                uint32_t off = (uint32_t)(row << 7) + (cB ^ ((uint32_t)(row & 7) << 4));
                ldsm4(bH[g16], baseB + off);
            }
            #pragma unroll
            for (int f = 0; f < 4; f++) {
                #pragma unroll
                for (int g16 = 0; g16 < 4; g16++) {
                    #pragma unroll
                    for (int p = 0; p < 2; p++) {
                        float* cc = acc[f][g16 * 2 + p];
                        mma16816h(cc, aF[f], bH[g16][2*p], bH[g16][2*p+1]);
                    }
                }
            }
        }
    }

    // ---- epilogue: bias + fp16 store ----
    #pragma unroll
    for (int f = 0; f < 4; f++) {
        #pragma unroll
        for (int g = 0; g < 8; g++) {
            int row = bm + wm + f * 16 + (lane >> 2);
            int col = bn + wn + g * 8 + (lane & 3) * 2;
            float b0 = bias[col], b1 = bias[col + 1];
            __half2 h0 = __floats2half2_rn(acc[f][g][0] + b0, acc[f][g][1] + b1);
            __half2 h1 = __floats2half2_rn(acc[f][g][2] + b0, acc[f][g][3] + b1);
            *(__half2*)(Cout + (size_t)row * GN + col)       = h0;
            *(__half2*)(Cout + (size_t)(row + 8) * GN + col) = h1;
        }
    }
}

// ---------------------------------------------------------------------------
// Fused attention (two-pass, champion): grid (GCH, B*NH), block 256.
// ---------------------------------------------------------------------------
#define SCHUNK (S / GCH)   // 256
#define RPW (SCHUNK / 8)   // 32 rows per warp

__global__ __launch_bounds__(256) void gl_attn(
    const float* __restrict__ mask, float* __restrict__ out)
{
    const int ch = blockIdx.x;
    const int bh = blockIdx.y;
    const int b  = bh / NH;
    const int h  = bh % NH;

    __shared__ float sq0[D], sk0[D], sv0[D];
    __shared__ float gsc[SCHUNK];
    __shared__ float sp0[SCHUNK], sp1[SCHUNK];
    __shared__ float red[8];
    __shared__ float vwarp[8][D];

    const int tid  = threadIdx.x;
    const int lane = tid & 31;
    const int w    = tid >> 5;

    const size_t base0 = ((size_t)b * S) * H + (size_t)h * D;
    if (tid < D) {
        sq0[tid] = __half2float(g_q[base0 + tid]);
        sk0[tid] = __half2float(g_k[base0 + tid]);
        sv0[tid] = __half2float(g_v[base0 + tid]);
    }
    __syncthreads();

    const float q00 = sq0[2 * lane], q01 = sq0[2 * lane + 1];
    const float k00 = sk0[2 * lane], k01 = sk0[2 * lane + 1];
    const float v00 = sv0[2 * lane], v01 = sv0[2 * lane + 1];

    const int row0 = w * RPW;
    const int s0   = ch * SCHUNK + row0;

    // phase 1: scores (global + local 2-way softmax)
    #pragma unroll 2
    for (int i = 0; i < RPW; i++) {
        const int s = s0 + i;
        const size_t bs = ((size_t)b * S + s) * H + (size_t)h * D;
        float2 q2 = __half22float2(((const __half2*)(g_q + bs))[lane]);
        float2 k2 = __half22float2(((const __half2*)(g_k + bs))[lane]);

        float dg = q00 * k2.x + q01 * k2.y;
        float ds = q2.x * k2.x + q2.y * k2.y;
        float dl = q2.x * k00 + q2.y * k01;
        #pragma unroll
        for (int o = 16; o; o >>= 1) {
            dg += __shfl_xor_sync(~0u, dg, o);
            ds += __shfl_xor_sync(~0u, ds, o);
            dl += __shfl_xor_sync(~0u, dl, o);
        }
        if (lane == 0) {
            gsc[row0 + i] = dg * SCALE + mask[(size_t)b * S + s];
            float ps = ds * SCALE, pg = dl * SCALE;
            float m  = fmaxf(ps, pg);
            float e0 = expf(ps - m), e1 = expf(pg - m);
            float inv = 1.f / (e0 + e1);
            sp0[row0 + i] = e0 * inv;
            sp1[row0 + i] = e1 * inv;
        }
    }
    __syncthreads();

    // phase 2: block softmax stats over SCHUNK=256 scores
    float lm = gsc[tid];
    #pragma unroll
    for (int o = 16; o; o >>= 1) lm = fmaxf(lm, __shfl_xor_sync(~0u, lm, o));
    if (lane == 0) red[w] = lm;
    __syncthreads();
    float bmax = red[0];
    #pragma unroll
    for (int ww = 1; ww < 8; ww++) bmax = fmaxf(bmax, red[ww]);
    __syncthreads();

    float e0 = expf(gsc[tid] - bmax);
    gsc[tid] = e0;
    float ls = e0;
    #pragma unroll
    for (int o = 16; o; o >>= 1) ls += __shfl_xor_sync(~0u, ls, o);
    if (lane == 0) red[w] = ls;
    __syncthreads();
    float bsum = 0.f;
    #pragma unroll
    for (int ww = 0; ww < 8; ww++) bsum += red[ww];

    // phase 3: V pass — local output + global V accumulation
    float a0 = 0.f, a1 = 0.f;
    #pragma unroll 2
    for (int i = 0; i < RPW; i++) {
        const int s = s0 + i;
        const size_t bs = ((size_t)b * S + s) * H + (size_t)h * D;
        float2 v2 = __half22float2(((const __half2*)(g_v + bs))[lane]);
        float pe = gsc[row0 + i];
        a0 = fmaf(pe, v2.x, a0);
        a1 = fmaf(pe, v2.y, a1);
        if (s != 0) {
            float p0 = sp0[row0 + i];
            float p1 = sp1[row0 + i];
            float2 o2 = make_float2(p0 * v2.x + p1 * v00,
                                    p0 * v2.y + p1 * v01);
            ((float2*)(out + bs))[lane] = o2;
            if (lane == 0) {
                size_t li = CTX_ELEMS + ((size_t)bh * (S - 1) + (s - 1)) * 2;
                out[li]     = p0;
                out[li + 1] = p1;
            }
        }
    }
    vwarp[w][2 * lane]     = a0;
    vwarp[w][2 * lane + 1] = a1;
    __syncthreads();

    if (tid < D) {
        float vs = 0.f;
        #pragma unroll
        for (int ww = 0; ww < 8; ww++) vs += vwarp[ww][tid];
        g_pvac[bh][ch][tid] = vs;
    }
    if (tid == 0) {
        g_pmax[bh][ch] = bmax;
        g_psum[bh][ch] = bsum;
    }
}

__global__ __launch_bounds__(64) void gattn_combine(float* __restrict__ out)
{
    const int bh = blockIdx.x;
    const int b  = bh / NH;
    const int h  = bh % NH;
    const int tid = threadIdx.x;

    float M = -INFINITY;
    #pragma unroll
    for (int c = 0; c < GCH; c++) M = fmaxf(M, g_pmax[bh][c]);
    float denom = 0.f, vs = 0.f;
    #pragma unroll
    for (int c = 0; c < GCH; c++) {
        float sc = expf(g_pmax[bh][c] - M);
        denom += g_psum[bh][c] * sc;
        vs    += g_pvac[bh][c][tid] * sc;
    }
    out[((size_t)b * S) * H + h * D + tid] = vs / denom;
}

// ---------------------------------------------------------------------------
extern "C" void kernel_launch(void* const* d_in, const int* in_sizes, int n_in,
                              void* d_out, int out_size)
{
    const float* hidden = (const float*)d_in[0];
    const float* mask   = (const float*)d_in[1];
    const float* Wq     = (const float*)d_in[2];
    const float* bq     = (const float*)d_in[3];
    const float* Wk     = (const float*)d_in[4];
    const float* bk     = (const float*)d_in[5];
    const float* Wv     = (const float*)d_in[6];
    const float* bv     = (const float*)d_in[7];
    float* out = (float*)d_out;

    split_all<<<(TOTN8 + 255) / 256, 256>>>(hidden, Wq, Wk, Wv);

    cudaFuncSetAttribute(qkv_gemm_mma, cudaFuncAttributeMaxDynamicSharedMemorySize, GSMEM);
    dim3 ggrid(GN / TN, GM / TM, 3);   // (8, 128, 3) = 3072 CTAs, 2/SM
    qkv_gemm_mma<<<ggrid, 128, GSMEM>>>(bq, bk, bv);

    dim3 agrid(GCH, B * NH);
    gl_attn<<<agrid, 256>>>(mask, out);
    gattn_combine<<<B * NH, 64>>>(out);
}